// round 10
// baseline (speedup 1.0000x reference)
#include <cuda_runtime.h>
#include <cuda_bf16.h>

// Problem constants
#define B    8
#define HIN  256
#define WIN  256
#define CV4  16      // C/4 float4 chunks per pixel (C=64)
#define HP   64
#define WP   64

__device__ __forceinline__ void acc4(float4& a, const float4 v) {
    a.x += v.x; a.y += v.y; a.z += v.z; a.w += v.w;
}
__device__ __forceinline__ float4 blend2(float4 p, float wp, float4 q, float wq) {
    float4 r;
    r.x = p.x * wp + q.x * wq;
    r.y = p.y * wp + q.y * wq;
    r.z = p.z * wp + q.z * wq;
    r.w = p.w * wp + q.w * wq;
    return r;
}
__device__ __forceinline__ float d2s(float d) {
    if (d < 5.5f)   return (d - 2.0f) * (1.0f / 3.5f);
    if (d > 249.5f) return (d - 249.5f) * (1.0f / 3.5f) + 62.0f;
    return (d - 1.5f) * 0.25f;
}

// ---------------------------------------------------------------------------
// Fully fused pool(6x6,s4,SAME) + unaverage-upsample(x4).
// CTA = (b, jj in 0..31, h in 0..7):
//   Phase 1: compute pooled rows {2jj, 2jj+1, 2jj+2} x pooled cols
//            [8h-1 .. 8h+8] (10, out-of-range zeroed) x 16 c4 into smem,
//            each value directly from its <=6x6 input window (L1/L2 serve
//            overlap; DRAM reads each input line once chip-wide).
//   Phase 2: blend + store dest rows [8jj+2 .. 8jj+9] (y<2 / y>253 handled
//            by edge jj's) x dest cols [32h .. 32h+31].
// Dest-row coverage: jj=0 also covers y=0,1 (6 rows for rr=0); jj=31 rr=1
// covers only y=254,255. Every y in [0,256) is written exactly once.
// ---------------------------------------------------------------------------
#define NPR   3
#define NKC   10
#define NVAL  (NPR * NKC * CV4)   // 480

__global__ __launch_bounds__(256, 7) void fused_kernel(const float4* __restrict__ in4,
                                                       float4* __restrict__ out4) {
    __shared__ float4 sp[NVAL];   // [pr][kcol][c4], 7.7 KB

    int bid = blockIdx.x;         // ((b*32)+jj)*8 + h
    int h  = bid & 7;
    int jj = (bid >> 3) & 31;
    int b  = bid >> 8;

    int t = threadIdx.x;

    // ---------------- Phase 1: pooled values ----------------
    #pragma unroll 1
    for (int vv = t; vv < NVAL; vv += 256) {
        int c4   = vv & 15;
        int rest = vv >> 4;       // 0..29
        int kcol = rest % NKC;    // 0..9
        int pr   = rest / NKC;    // 0..2
        int prow = 2 * jj + pr;
        int k    = 8 * h - 1 + kcol;

        float4 s = make_float4(0.f, 0.f, 0.f, 0.f);
        if (prow < HP && (unsigned)k < (unsigned)WP) {
            int rb = 4 * prow - 1;
            int cb = 4 * k - 1;
            if (prow >= 1 && prow <= 62 && k >= 1 && k <= 62) {
                const float4* pp = in4 + (((size_t)b * HIN + rb) * WIN + cb) * CV4 + c4;
                #pragma unroll
                for (int r = 0; r < 6; ++r) {
                    #pragma unroll
                    for (int cc = 0; cc < 6; ++cc)
                        acc4(s, __ldg(pp + ((size_t)r * WIN + cc) * CV4));
                }
                s.x *= (1.0f / 36.0f); s.y *= (1.0f / 36.0f);
                s.z *= (1.0f / 36.0f); s.w *= (1.0f / 36.0f);
            } else {
                int rlo = rb < 0 ? 0 : rb;
                int rhi = rb + 6 > HIN ? HIN : rb + 6;
                int clo = cb < 0 ? 0 : cb;
                int chi = cb + 6 > WIN ? WIN : cb + 6;
                for (int r = rlo; r < rhi; ++r)
                    for (int cc = clo; cc < chi; ++cc)
                        acc4(s, __ldg(in4 + (((size_t)b * HIN + r) * WIN + cc) * CV4 + c4));
                float inv = 1.0f / (float)((rhi - rlo) * (chi - clo));
                s.x *= inv; s.y *= inv; s.z *= inv; s.w *= inv;
            }
        }
        sp[vv] = s;   // vv == (pr*NKC + kcol)*CV4 + c4
    }
    __syncthreads();

    // ---------------- Phase 2: blend + store ----------------
    int c4 = t & 15;
    int qq = (t >> 4) & 7;        // pooled col group within h
    int rr = t >> 7;              // 0 or 1 (g = 2jj + rr)
    int q  = 8 * h + qq;          // dest cols 4q..4q+3; taps pooled q-1..q+1

    int ystart, nrows;
    if (jj == 0 && rr == 0)       { ystart = 0;   nrows = 6; }
    else if (jj == 31 && rr == 1) { ystart = 254; nrows = 2; }
    else                          { ystart = 8 * jj + 4 * rr + 2; nrows = 4; }

    bool interior_x = (q >= 2 && q <= 61);
    const float4 z = make_float4(0.f, 0.f, 0.f, 0.f);

    #pragma unroll 1
    for (int i = 0; i < nrows; ++i) {
        int y = ystart + i;
        float sr  = d2s((float)y);
        float r0f = floorf(sr);
        int   r0  = (int)r0f;
        float fr  = sr - r0f;
        float wr0 = 1.0f - fr;
        int plo = r0 - 2 * jj;    // -1, 0, or 1; plo+1 in 0..2

        float4 T[3];
        #pragma unroll
        for (int i2 = 0; i2 < 3; ++i2) {
            // tap pooled col q-1+i2 -> smem kcol = qq + i2
            float4 a  = (plo >= 0) ? sp[(plo * NKC + qq + i2) * CV4 + c4] : z;
            float4 bb = sp[((plo + 1) * NKC + qq + i2) * CV4 + c4];
            T[i2] = blend2(a, wr0, bb, fr);
        }

        float4* op = out4 + (((size_t)b * HIN + y) * WIN + 4 * q) * CV4 + c4;
        if (interior_x) {
            op[0 * CV4] = blend2(T[0], 0.375f, T[1], 0.625f);
            op[1 * CV4] = blend2(T[0], 0.125f, T[1], 0.875f);
            op[2 * CV4] = blend2(T[1], 0.875f, T[2], 0.125f);
            op[3 * CV4] = blend2(T[1], 0.625f, T[2], 0.375f);
        } else {
            #pragma unroll
            for (int m = 0; m < 4; ++m) {
                float sc  = d2s((float)(4 * q + m));
                float c0f = floorf(sc);
                float fc  = sc - c0f;
                int idx = (int)c0f - (q - 1);   // 0 or 1
                float4 lo = idx ? T[1] : T[0];
                float4 hi = idx ? T[2] : T[1];
                op[m * CV4] = blend2(lo, 1.0f - fc, hi, fc);
            }
        }
    }
}

extern "C" void kernel_launch(void* const* d_in, const int* in_sizes, int n_in,
                              void* d_out, int out_size) {
    const float4* in4 = (const float4*)d_in[0];
    float4* out4 = (float4*)d_out;

    fused_kernel<<<B * 32 * 8, 256>>>(in4, out4);   // 2048 CTAs
}

// round 11
// speedup vs baseline: 1.1438x; 1.1438x over previous
#include <cuda_runtime.h>
#include <cuda_fp16.h>
#include <cuda_bf16.h>

// Problem constants
#define B    8
#define HIN  256
#define WIN  256
#define CV4  16      // C/4 channel chunks per pixel (C=64)
#define HP   64
#define WP   64

// Static device scratch: fp16 column sums (16.7 MB) + fp16 pooled (4 MB)
__device__ uint2 g_colsum[B * HP * WIN * CV4];
__device__ uint2 g_pooled[B * HP * WP  * CV4];

__device__ __forceinline__ void acc4(float4& a, const float4 v) {
    a.x += v.x; a.y += v.y; a.z += v.z; a.w += v.w;
}
__device__ __forceinline__ float4 blend2(float4 p, float wp, float4 q, float wq) {
    float4 r;
    r.x = p.x * wp + q.x * wq;
    r.y = p.y * wp + q.y * wq;
    r.z = p.z * wp + q.z * wq;
    r.w = p.w * wp + q.w * wq;
    return r;
}
__device__ __forceinline__ uint2 pack_h4(float4 v) {
    __half2 lo = __floats2half2_rn(v.x, v.y);
    __half2 hi = __floats2half2_rn(v.z, v.w);
    uint2 u;
    u.x = *reinterpret_cast<unsigned int*>(&lo);
    u.y = *reinterpret_cast<unsigned int*>(&hi);
    return u;
}
__device__ __forceinline__ float4 unpack_h4(uint2 u) {
    __half2 lo = *reinterpret_cast<__half2*>(&u.x);
    __half2 hi = *reinterpret_cast<__half2*>(&u.y);
    float2 a = __half22float2(lo);
    float2 b = __half22float2(hi);
    return make_float4(a.x, a.y, b.x, b.y);
}

// ---------------------------------------------------------------------------
// K1: column pool (sum over y-window of 6, stride 4, pad 1/1), fp16 output.
// Streaming, one task per thread — the R3-proven 76%-DRAM shape.
// ---------------------------------------------------------------------------
__global__ __launch_bounds__(256) void colpool_kernel(const float4* __restrict__ in4) {
    int tid = blockIdx.x * 256 + threadIdx.x;   // B*HP*WIN*CV4 = 2,097,152
    int c4 = tid & 15;
    int x  = (tid >> 4) & 255;
    int oy = (tid >> 12) & 63;
    int b  = tid >> 18;

    int r0 = oy * 4 - 1;
    const float4* p = in4 + (((size_t)b * HIN) * WIN + x) * CV4 + c4;

    float4 s = make_float4(0.f, 0.f, 0.f, 0.f);
    if (oy != 0 && oy != 63) {
        const float4* q = p + (size_t)r0 * WIN * CV4;
        #pragma unroll
        for (int j = 0; j < 6; ++j)
            acc4(s, __ldg(q + (size_t)j * WIN * CV4));
    } else {
        #pragma unroll
        for (int j = 0; j < 6; ++j) {
            int r = r0 + j;
            if ((unsigned)r < 256u)
                acc4(s, __ldg(p + (size_t)r * WIN * CV4));
        }
    }
    // colsum layout: ((b*HP + oy)*WIN + x)*CV4 + c4 == tid
    g_colsum[tid] = pack_h4(s);
}

// ---------------------------------------------------------------------------
// K2: row pool (sum over x-window of 6 of fp16 colsums, fp32 accumulate)
// + divide by valid count, fp16 output. Streaming, one task per thread.
// Colsums are L2-resident (written by K1 just before).
// ---------------------------------------------------------------------------
__global__ __launch_bounds__(256) void rowpool_kernel() {
    int tid = blockIdx.x * 256 + threadIdx.x;   // B*HP*WP*CV4 = 524,288
    int c4 = tid & 15;
    int ox = (tid >> 4) & 63;
    int oy = (tid >> 10) & 63;
    int b  = tid >> 16;

    int x0 = ox * 4 - 1;
    const uint2* p = g_colsum + (((size_t)b * HP + oy) * WIN) * CV4 + c4;

    float4 s = make_float4(0.f, 0.f, 0.f, 0.f);
    if (ox != 0 && ox != 63) {
        const uint2* q = p + (size_t)x0 * CV4;
        #pragma unroll
        for (int j = 0; j < 6; ++j)
            acc4(s, unpack_h4(__ldg(q + (size_t)j * CV4)));
    } else {
        #pragma unroll
        for (int j = 0; j < 6; ++j) {
            int x = x0 + j;
            if ((unsigned)x < 256u)
                acc4(s, unpack_h4(__ldg(p + (size_t)x * CV4)));
        }
    }

    int nr = 6 - (oy == 0) - (oy == 63);
    int nc = 6 - (ox == 0) - (ox == 63);
    float inv = 1.0f / (float)(nr * nc);
    // pooled layout: ((b*HP+oy)*WP+ox)*CV4 + c4 == tid
    g_pooled[tid] = pack_h4(make_float4(s.x * inv, s.y * inv, s.z * inv, s.w * inv));
}

// ---------------------------------------------------------------------------
// K3: unaverage pool (x4 upsample), direct streaming (R9-proven: 22.6us).
// One thread = 8 consecutive x outputs (two k-groups) x one channel chunk.
// ---------------------------------------------------------------------------
__device__ __forceinline__ float d2s(float d) {
    if (d < 5.5f)   return (d - 2.0f) * (1.0f / 3.5f);
    if (d > 249.5f) return (d - 249.5f) * (1.0f / 3.5f) + 62.0f;
    return (d - 1.5f) * 0.25f;
}

__global__ __launch_bounds__(256, 6) void up_kernel(float4* __restrict__ out4) {
    int tid = blockIdx.x * 256 + threadIdx.x;   // B*256*32*16 = 1,048,576
    int c4 = tid & 15;
    int kk = (tid >> 4) & 31;
    int y  = (tid >> 9) & 255;
    int b  = tid >> 17;

    int k0 = kk * 2;

    float sr  = d2s((float)y);
    float r0f = floorf(sr);
    int   r0  = (int)r0f;
    float fr  = sr - r0f;
    bool rv0 = (r0 >= 0);
    bool rv1 = (r0 < HP - 1);
    float wr0 = 1.0f - fr;

    const uint2* pbase = g_pooled + ((size_t)b * HP * WP) * CV4 + c4;
    const uint2* rowA  = pbase + (size_t)(rv0 ? r0     : 0) * WP * CV4;
    const uint2* rowB  = pbase + (size_t)(rv1 ? r0 + 1 : 0) * WP * CV4;

    const float4 z = make_float4(0.f, 0.f, 0.f, 0.f);

    float4 T[4];
    #pragma unroll
    for (int i = 0; i < 4; ++i) {
        int col = k0 - 1 + i;
        bool cv = (unsigned)col < (unsigned)WP;
        float4 a  = (rv0 && cv) ? unpack_h4(__ldg(rowA + (size_t)col * CV4)) : z;
        float4 bb = (rv1 && cv) ? unpack_h4(__ldg(rowB + (size_t)col * CV4)) : z;
        T[i] = blend2(a, wr0, bb, fr);
    }

    float4* op = out4 + (((size_t)b * HIN + y) * WIN + k0 * 4) * CV4 + c4;

    if (kk >= 1 && kk <= 30) {
        op[0 * CV4] = blend2(T[0], 0.375f, T[1], 0.625f);
        op[1 * CV4] = blend2(T[0], 0.125f, T[1], 0.875f);
        op[2 * CV4] = blend2(T[1], 0.875f, T[2], 0.125f);
        op[3 * CV4] = blend2(T[1], 0.625f, T[2], 0.375f);
        op[4 * CV4] = blend2(T[1], 0.375f, T[2], 0.625f);
        op[5 * CV4] = blend2(T[1], 0.125f, T[2], 0.875f);
        op[6 * CV4] = blend2(T[2], 0.875f, T[3], 0.125f);
        op[7 * CV4] = blend2(T[2], 0.625f, T[3], 0.375f);
    } else {
        int x0 = k0 * 4;
        #pragma unroll
        for (int m = 0; m < 8; ++m) {
            float sc  = d2s((float)(x0 + m));
            float c0f = floorf(sc);
            float fc  = sc - c0f;
            int idx = (int)c0f - (k0 - 1);   // 0..2
            float4 lo = (idx == 0) ? T[0] : ((idx == 1) ? T[1] : T[2]);
            float4 hi = (idx == 0) ? T[1] : ((idx == 1) ? T[2] : T[3]);
            op[m * CV4] = blend2(lo, 1.0f - fc, hi, fc);
        }
    }
}

extern "C" void kernel_launch(void* const* d_in, const int* in_sizes, int n_in,
                              void* d_out, int out_size) {
    const float4* in4 = (const float4*)d_in[0];
    float4* out4 = (float4*)d_out;

    colpool_kernel<<<(B * HP * WIN * CV4) / 256, 256>>>(in4);   // 8192 CTAs
    rowpool_kernel<<<(B * HP * WP * CV4) / 256, 256>>>();       // 2048 CTAs
    up_kernel<<<(B * HIN * 32 * CV4) / 256, 256>>>(out4);       // 4096 CTAs
}

// round 12
// speedup vs baseline: 1.1743x; 1.0267x over previous
#include <cuda_runtime.h>
#include <cuda_fp16.h>
#include <cuda_bf16.h>

// Problem constants
#define B    8
#define HIN  256
#define WIN  256
#define CV4  16      // C/4 channel chunks per pixel (C=64)
#define HP   64
#define WP   64

// 4 MB pooled averages in fp16 — static device scratch
__device__ uint2 g_pooled[B * HP * WP * CV4];

__device__ __forceinline__ void acc4(float4& a, const float4 v) {
    a.x += v.x; a.y += v.y; a.z += v.z; a.w += v.w;
}
__device__ __forceinline__ float4 blend2(float4 p, float wp, float4 q, float wq) {
    float4 r;
    r.x = p.x * wp + q.x * wq;
    r.y = p.y * wp + q.y * wq;
    r.z = p.z * wp + q.z * wq;
    r.w = p.w * wp + q.w * wq;
    return r;
}
__device__ __forceinline__ uint2 pack_h4(float4 v) {
    __half2 lo = __floats2half2_rn(v.x, v.y);
    __half2 hi = __floats2half2_rn(v.z, v.w);
    uint2 u;
    u.x = *reinterpret_cast<unsigned int*>(&lo);
    u.y = *reinterpret_cast<unsigned int*>(&hi);
    return u;
}
__device__ __forceinline__ float4 unpack_h4(uint2 u) {
    __half2 lo = *reinterpret_cast<__half2*>(&u.x);
    __half2 hi = *reinterpret_cast<__half2*>(&u.y);
    float2 a = __half22float2(lo);
    float2 b = __half22float2(hi);
    return make_float4(a.x, a.y, b.x, b.y);
}

// ---------------------------------------------------------------------------
// K1: fused SAME avg-pool 6x6 stride 4 in ONE kernel.
// CTA = (b, oy, x-group g of 16 ox). 256 threads, occ 7, grid 2048
//   -> 1.98 waves of 148*7=1036 CTAs (near-perfect fill).
// Phase 1: 1056 column-sum tasks (66 x-cols [64g-1..64g+64] x 16 c4),
//          4.125 tasks/thread, 6 strided loads each (colpool's proven shape),
//          fp32 sums into 16.9 KB smem.
// Phase 2: one task/thread (16 ox x 16 c4): 6 LDS.128 + divide, fp16 store.
// ---------------------------------------------------------------------------
#define GSPAN 66
#define NT1   (GSPAN * CV4)    // 1056

__global__ __launch_bounds__(256, 7) void pool_kernel(const float4* __restrict__ in4) {
    __shared__ float4 cs[NT1];

    int bid = blockIdx.x;      // ((b*64)+oy)*4 + g
    int g  = bid & 3;
    int oy = (bid >> 2) & 63;
    int b  = bid >> 8;

    int t = threadIdx.x;
    int r0 = 4 * oy - 1;
    bool yint = (oy != 0) && (oy != 63);
    int xbase = 64 * g - 1;

    const float4* base = in4 + ((size_t)b * HIN * WIN) * CV4;
    const size_t RS = (size_t)WIN * CV4;

    // Phase 1: column sums
    #pragma unroll 1
    for (int v = t; v < NT1; v += 256) {
        int c4 = v & 15;
        int xl = v >> 4;
        int x  = xbase + xl;
        float4 s = make_float4(0.f, 0.f, 0.f, 0.f);
        if ((unsigned)x < 256u) {
            const float4* p = base + (size_t)x * CV4 + c4;
            if (yint) {
                const float4* qq = p + (size_t)r0 * RS;
                float4 v0 = __ldg(qq + 0 * RS);
                float4 v1 = __ldg(qq + 1 * RS);
                float4 v2 = __ldg(qq + 2 * RS);
                acc4(s, v0); acc4(s, v1); acc4(s, v2);
                float4 v3 = __ldg(qq + 3 * RS);
                float4 v4 = __ldg(qq + 4 * RS);
                float4 v5 = __ldg(qq + 5 * RS);
                acc4(s, v3); acc4(s, v4); acc4(s, v5);
            } else {
                #pragma unroll
                for (int j = 0; j < 6; ++j) {
                    int r = r0 + j;
                    if ((unsigned)r < 256u)
                        acc4(s, __ldg(p + (size_t)r * RS));
                }
            }
        }
        cs[v] = s;
    }
    __syncthreads();

    // Phase 2: exactly one output per thread
    {
        int c4  = t & 15;
        int oxl = t >> 4;          // 0..15
        int ox  = 16 * g + oxl;

        // taps: cs[(4*oxl + j)*16 + c4], global x = 4*ox - 1 + j
        float4 s = make_float4(0.f, 0.f, 0.f, 0.f);
        if (ox != 0) acc4(s, cs[(4 * oxl + 0) * CV4 + c4]);
        acc4(s, cs[(4 * oxl + 1) * CV4 + c4]);
        acc4(s, cs[(4 * oxl + 2) * CV4 + c4]);
        acc4(s, cs[(4 * oxl + 3) * CV4 + c4]);
        acc4(s, cs[(4 * oxl + 4) * CV4 + c4]);
        if (ox != 63) acc4(s, cs[(4 * oxl + 5) * CV4 + c4]);

        int nr = 6 - (oy == 0) - (oy == 63);
        int nc = 6 - (ox == 0) - (ox == 63);
        float inv = 1.0f / (float)(nr * nc);
        g_pooled[(((size_t)b * HP + oy) * WP + ox) * CV4 + c4] =
            pack_h4(make_float4(s.x * inv, s.y * inv, s.z * inv, s.w * inv));
    }
}

// ---------------------------------------------------------------------------
// K2: unaverage pool (x4 upsample), direct streaming — byte-identical to the
// R9-proven 22.6us version (fp16 taps).
// ---------------------------------------------------------------------------
__device__ __forceinline__ float d2s(float d) {
    if (d < 5.5f)   return (d - 2.0f) * (1.0f / 3.5f);
    if (d > 249.5f) return (d - 249.5f) * (1.0f / 3.5f) + 62.0f;
    return (d - 1.5f) * 0.25f;
}

__global__ __launch_bounds__(256, 6) void up_kernel(float4* __restrict__ out4) {
    int tid = blockIdx.x * 256 + threadIdx.x;   // B*256*32*16 = 1,048,576
    int c4 = tid & 15;
    int kk = (tid >> 4) & 31;
    int y  = (tid >> 9) & 255;
    int b  = tid >> 17;

    int k0 = kk * 2;

    float sr  = d2s((float)y);
    float r0f = floorf(sr);
    int   r0  = (int)r0f;
    float fr  = sr - r0f;
    bool rv0 = (r0 >= 0);
    bool rv1 = (r0 < HP - 1);
    float wr0 = 1.0f - fr;

    const uint2* pbase = g_pooled + ((size_t)b * HP * WP) * CV4 + c4;
    const uint2* rowA  = pbase + (size_t)(rv0 ? r0     : 0) * WP * CV4;
    const uint2* rowB  = pbase + (size_t)(rv1 ? r0 + 1 : 0) * WP * CV4;

    const float4 z = make_float4(0.f, 0.f, 0.f, 0.f);

    float4 T[4];
    #pragma unroll
    for (int i = 0; i < 4; ++i) {
        int col = k0 - 1 + i;
        bool cv = (unsigned)col < (unsigned)WP;
        float4 a  = (rv0 && cv) ? unpack_h4(__ldg(rowA + (size_t)col * CV4)) : z;
        float4 bb = (rv1 && cv) ? unpack_h4(__ldg(rowB + (size_t)col * CV4)) : z;
        T[i] = blend2(a, wr0, bb, fr);
    }

    float4* op = out4 + (((size_t)b * HIN + y) * WIN + k0 * 4) * CV4 + c4;

    if (kk >= 1 && kk <= 30) {
        op[0 * CV4] = blend2(T[0], 0.375f, T[1], 0.625f);
        op[1 * CV4] = blend2(T[0], 0.125f, T[1], 0.875f);
        op[2 * CV4] = blend2(T[1], 0.875f, T[2], 0.125f);
        op[3 * CV4] = blend2(T[1], 0.625f, T[2], 0.375f);
        op[4 * CV4] = blend2(T[1], 0.375f, T[2], 0.625f);
        op[5 * CV4] = blend2(T[1], 0.125f, T[2], 0.875f);
        op[6 * CV4] = blend2(T[2], 0.875f, T[3], 0.125f);
        op[7 * CV4] = blend2(T[2], 0.625f, T[3], 0.375f);
    } else {
        int x0 = k0 * 4;
        #pragma unroll
        for (int m = 0; m < 8; ++m) {
            float sc  = d2s((float)(x0 + m));
            float c0f = floorf(sc);
            float fc  = sc - c0f;
            int idx = (int)c0f - (k0 - 1);   // 0..2
            float4 lo = (idx == 0) ? T[0] : ((idx == 1) ? T[1] : T[2]);
            float4 hi = (idx == 0) ? T[1] : ((idx == 1) ? T[2] : T[3]);
            op[m * CV4] = blend2(lo, 1.0f - fc, hi, fc);
        }
    }
}

extern "C" void kernel_launch(void* const* d_in, const int* in_sizes, int n_in,
                              void* d_out, int out_size) {
    const float4* in4 = (const float4*)d_in[0];
    float4* out4 = (float4*)d_out;

    pool_kernel<<<B * HP * 4, 256>>>(in4);                // 2048 CTAs
    up_kernel<<<(B * HIN * 32 * CV4) / 256, 256>>>(out4); // 4096 CTAs
}